// round 4
// baseline (speedup 1.0000x reference)
#include <cuda_runtime.h>

#define NN 100000
#define NE 600000
#define CIN 16
#define HW 48
#define NL 5
#define EB ((NE + 127) / 128)

// ---- scratch (device globals: allocation-guard safe) ----
__device__ float  g_x1[NN * CIN];
__device__ float  g_x2[NN * CIN];
__device__ float  g_agg[NN * CIN];
__device__ float  g_cnt[NN];
__device__ float  g_ef1[(size_t)NE * HW];   // 115 MB intermediate edge features
__device__ double g_sl[2];

// ---------------------------------------------------------------------------
__global__ void zero_kernel(int phase) {
    int i = blockIdx.x * blockDim.x + threadIdx.x;
    if (i < NN * CIN) g_agg[i] = 0.f;
    if (i < NN)       g_cnt[i] = 0.f;
    if (phase == 0 && i < 2) g_sl[i] = 0.0;
}

// ---------------------------------------------------------------------------
// NodeConv message + scatter: per edge, MLP(concat(x[dst],x[src],angle)),
// atomic-add into g_agg[dst], count into g_cnt[dst].
__global__ __launch_bounds__(128) void nc_kernel(
    const float* __restrict__ x, const int* __restrict__ ei,
    const float* __restrict__ ang,
    const float* __restrict__ w0, const float* __restrict__ b0,
    const float* __restrict__ wh, const float* __restrict__ bh)
{
    __shared__ float sw0[33 * 16];
    __shared__ float sb0[16];
    __shared__ float swh[5 * 16 * 16];
    __shared__ float sbh[5 * 16];
    int t = threadIdx.x;
    for (int i = t; i < 33 * 16; i += 128) sw0[i] = w0[i];
    for (int i = t; i < 16;      i += 128) sb0[i] = b0[i];
    for (int i = t; i < 5 * 256; i += 128) swh[i] = wh[i];
    for (int i = t; i < 80;      i += 128) sbh[i] = bh[i];
    __syncthreads();

    int e = blockIdx.x * 128 + t;
    if (e >= NE) return;
    int s = ei[e];
    int d = ei[NE + e];

    float in[33];
    const float4* xd4 = (const float4*)(x + (size_t)d * CIN);
    const float4* xs4 = (const float4*)(x + (size_t)s * CIN);
    #pragma unroll
    for (int q = 0; q < 4; q++) {
        float4 v = xd4[q];
        in[q * 4 + 0] = v.x; in[q * 4 + 1] = v.y; in[q * 4 + 2] = v.z; in[q * 4 + 3] = v.w;
    }
    #pragma unroll
    for (int q = 0; q < 4; q++) {
        float4 v = xs4[q];
        in[16 + q * 4 + 0] = v.x; in[16 + q * 4 + 1] = v.y;
        in[16 + q * 4 + 2] = v.z; in[16 + q * 4 + 3] = v.w;
    }
    in[32] = ang[e];

    float acc[16], h[16];
    #pragma unroll
    for (int j = 0; j < 16; j++) acc[j] = sb0[j];
    #pragma unroll
    for (int k = 0; k < 33; k++) {
        float v = in[k];
        #pragma unroll
        for (int j = 0; j < 16; j++) acc[j] += v * sw0[k * 16 + j];
    }
    #pragma unroll
    for (int j = 0; j < 16; j++) h[j] = fmaxf(acc[j], 0.f);

    #pragma unroll 1
    for (int l = 0; l < NL; l++) {
        const float* wl = swh + l * 256;
        const float* bl = sbh + l * 16;
        #pragma unroll
        for (int j = 0; j < 16; j++) acc[j] = bl[j];
        #pragma unroll
        for (int k = 0; k < 16; k++) {
            float v = h[k];
            #pragma unroll
            for (int j = 0; j < 16; j++) acc[j] += v * wl[k * 16 + j];
        }
        #pragma unroll
        for (int j = 0; j < 16; j++) h[j] = fmaxf(acc[j], 0.f);
    }

    #pragma unroll
    for (int j = 0; j < 16; j++) atomicAdd(&g_agg[(size_t)d * CIN + j], h[j]);
    atomicAdd(&g_cnt[d], 1.f);
}

// ---------------------------------------------------------------------------
__global__ void div_kernel(float* __restrict__ out) {
    int i = blockIdx.x * blockDim.x + threadIdx.x;
    if (i >= NN * CIN) return;
    float c = g_cnt[i / CIN];
    out[i] = g_agg[i] / fmaxf(c, 1.f);
}

// ---------------------------------------------------------------------------
// EdgeConv: both endpoint orders through the shared MLP, side-loss sumsq,
// fe = 0.5*(f1+f2), then combine layer.
// IS_EC1=1: combine [fe, action](49) -> 48, out = g_ef1
// IS_EC1=0: combine [fe, ef1](96)   -> 1,  out = d_out
template <int IS_EC1>
__global__ __launch_bounds__(128) void ec_kernel(
    const float* __restrict__ x, const int* __restrict__ ei,
    const float* __restrict__ extra,
    const float* __restrict__ w0, const float* __restrict__ b0,
    const float* __restrict__ wh, const float* __restrict__ bh,
    const float* __restrict__ wc, const float* __restrict__ bc,
    float* __restrict__ out, int sli)
{
    extern __shared__ float smem[];
    const int WC = IS_EC1 ? 49 * 48 : 96;
    const int BC = IS_EC1 ? 48 : 1;
    float* sw0 = smem;                 // 32*48
    float* sb0 = sw0 + 32 * 48;        // 48
    float* swh = sb0 + 48;             // 5*48*48
    float* sbh = swh + 5 * 48 * 48;    // 5*48
    float* swc = sbh + 5 * 48;         // WC
    float* sbc = swc + WC;             // BC

    int t = threadIdx.x;
    for (int i = t; i < 32 * 48;     i += 128) sw0[i] = w0[i];
    for (int i = t; i < 48;          i += 128) sb0[i] = b0[i];
    for (int i = t; i < 5 * 48 * 48; i += 128) swh[i] = wh[i];
    for (int i = t; i < 5 * 48;      i += 128) sbh[i] = bh[i];
    for (int i = t; i < WC;          i += 128) swc[i] = wc[i];
    for (int i = t; i < BC;          i += 128) sbc[i] = bc[i];
    __syncthreads();

    int e = blockIdx.x * 128 + t;
    float sq = 0.f;
    if (e < NE) {
        int s = ei[e];
        int d = ei[NE + e];

        float xs[16], xd[16];
        {
            const float4* a4 = (const float4*)(x + (size_t)s * CIN);
            const float4* b4 = (const float4*)(x + (size_t)d * CIN);
            #pragma unroll
            for (int q = 0; q < 4; q++) {
                float4 v = a4[q];
                xs[q * 4 + 0] = v.x; xs[q * 4 + 1] = v.y; xs[q * 4 + 2] = v.z; xs[q * 4 + 3] = v.w;
                float4 w = b4[q];
                xd[q * 4 + 0] = w.x; xd[q * 4 + 1] = w.y; xd[q * 4 + 2] = w.z; xd[q * 4 + 3] = w.w;
            }
        }

        float f1[48], h[48];
        // pass 0: f1 = MLP([x[dst], x[src]]); pass 1: f2 = MLP([x[src], x[dst]])
        #pragma unroll 1
        for (int pass = 0; pass < 2; pass++) {
            float acc[48];
            #pragma unroll
            for (int j = 0; j < 48; j++) acc[j] = sb0[j];
            #pragma unroll
            for (int k = 0; k < 16; k++) {
                float v = pass ? xs[k] : xd[k];
                #pragma unroll
                for (int j = 0; j < 48; j++) acc[j] += v * sw0[k * 48 + j];
            }
            #pragma unroll
            for (int k = 0; k < 16; k++) {
                float v = pass ? xd[k] : xs[k];
                #pragma unroll
                for (int j = 0; j < 48; j++) acc[j] += v * sw0[(16 + k) * 48 + j];
            }
            #pragma unroll
            for (int j = 0; j < 48; j++) h[j] = fmaxf(acc[j], 0.f);

            #pragma unroll 1
            for (int l = 0; l < NL; l++) {
                const float* wl = swh + l * 2304;
                const float* bl = sbh + l * 48;
                #pragma unroll
                for (int j = 0; j < 48; j++) acc[j] = bl[j];
                #pragma unroll
                for (int k = 0; k < 48; k++) {
                    float v = h[k];
                    #pragma unroll
                    for (int j = 0; j < 48; j++) acc[j] += v * wl[k * 48 + j];
                }
                #pragma unroll
                for (int j = 0; j < 48; j++) h[j] = fmaxf(acc[j], 0.f);
            }
            if (pass == 0) {
                #pragma unroll
                for (int j = 0; j < 48; j++) f1[j] = h[j];
            }
        }

        // side loss + fe (overwrite f1 with fe)
        #pragma unroll
        for (int j = 0; j < 48; j++) {
            float dlt = f1[j] - h[j];
            sq += dlt * dlt;
            f1[j] = 0.5f * (f1[j] + h[j]);
        }

        if (IS_EC1) {
            float a = extra[e];
            #pragma unroll 1
            for (int jc = 0; jc < 12; jc++) {
                float o0 = sbc[jc * 4 + 0] + a * swc[48 * 48 + jc * 4 + 0];
                float o1 = sbc[jc * 4 + 1] + a * swc[48 * 48 + jc * 4 + 1];
                float o2 = sbc[jc * 4 + 2] + a * swc[48 * 48 + jc * 4 + 2];
                float o3 = sbc[jc * 4 + 3] + a * swc[48 * 48 + jc * 4 + 3];
                #pragma unroll
                for (int k = 0; k < 48; k++) {
                    float v = f1[k];
                    o0 += v * swc[k * 48 + jc * 4 + 0];
                    o1 += v * swc[k * 48 + jc * 4 + 1];
                    o2 += v * swc[k * 48 + jc * 4 + 2];
                    o3 += v * swc[k * 48 + jc * 4 + 3];
                }
                float4 o4 = make_float4(o0, o1, o2, o3);
                *(float4*)(out + (size_t)e * 48 + jc * 4) = o4;
            }
        } else {
            float o = sbc[0];
            #pragma unroll
            for (int k = 0; k < 48; k++) o += f1[k] * swc[k];
            const float* ef = extra + (size_t)e * 48;
            #pragma unroll
            for (int k = 0; k < 48; k++) o += ef[k] * swc[48 + k];
            out[e] = o;
        }
    }

    // side-loss reduction: warp shfl -> double atomic
    #pragma unroll
    for (int off = 16; off; off >>= 1)
        sq += __shfl_xor_sync(0xffffffffu, sq, off);
    if ((t & 31) == 0)
        atomicAdd(&g_sl[sli], (double)sq);
}

// ---------------------------------------------------------------------------
__global__ void fin_kernel(float* __restrict__ out) {
    double inv = 1.0 / ((double)NE * 48.0);
    out[NE] = (float)(0.5 * (g_sl[0] * inv + g_sl[1] * inv));
}

// ---------------------------------------------------------------------------
extern "C" void kernel_launch(void* const* d_in, const int* in_sizes, int n_in,
                              void* d_out, int out_size)
{
    const float* nf   = (const float*)d_in[0];
    const int*   ei   = (const int*)d_in[1];
    const float* ang  = (const float*)d_in[2];
    const float* act  = (const float*)d_in[4];
    const float* n1w0 = (const float*)d_in[5],  *n1b0 = (const float*)d_in[6];
    const float* n1wh = (const float*)d_in[7],  *n1bh = (const float*)d_in[8];
    const float* n2w0 = (const float*)d_in[9],  *n2b0 = (const float*)d_in[10];
    const float* n2wh = (const float*)d_in[11], *n2bh = (const float*)d_in[12];
    const float* e1w0 = (const float*)d_in[13], *e1b0 = (const float*)d_in[14];
    const float* e1wh = (const float*)d_in[15], *e1bh = (const float*)d_in[16];
    const float* e1wc = (const float*)d_in[17], *e1bc = (const float*)d_in[18];
    const float* e2w0 = (const float*)d_in[19], *e2b0 = (const float*)d_in[20];
    const float* e2wh = (const float*)d_in[21], *e2bh = (const float*)d_in[22];
    const float* e2wc = (const float*)d_in[23], *e2bc = (const float*)d_in[24];
    float* out = (float*)d_out;

    void *px1, *px2, *pef1;
    cudaGetSymbolAddress(&px1, g_x1);
    cudaGetSymbolAddress(&px2, g_x2);
    cudaGetSymbolAddress(&pef1, g_ef1);

    size_t sh1 = (size_t)(32 * 48 + 48 + 5 * 48 * 48 + 5 * 48 + 49 * 48 + 48) * sizeof(float);
    size_t sh2 = (size_t)(32 * 48 + 48 + 5 * 48 * 48 + 5 * 48 + 96 + 1) * sizeof(float);
    cudaFuncSetAttribute(ec_kernel<1>, cudaFuncAttributeMaxDynamicSharedMemorySize, (int)sh1);
    cudaFuncSetAttribute(ec_kernel<0>, cudaFuncAttributeMaxDynamicSharedMemorySize, (int)sh2);

    // NodeConv1 -> x1
    zero_kernel<<<6250, 256>>>(0);
    nc_kernel<<<EB, 128>>>(nf, ei, ang, n1w0, n1b0, n1wh, n1bh);
    div_kernel<<<6250, 256>>>((float*)px1);
    // EdgeConv1 -> ef1 (E x 48), sl[0]
    ec_kernel<1><<<EB, 128, sh1>>>((const float*)px1, ei, act,
                                   e1w0, e1b0, e1wh, e1bh, e1wc, e1bc,
                                   (float*)pef1, 0);
    // NodeConv2 -> x2
    zero_kernel<<<6250, 256>>>(1);
    nc_kernel<<<EB, 128>>>((const float*)px1, ei, ang, n2w0, n2b0, n2wh, n2bh);
    div_kernel<<<6250, 256>>>((float*)px2);
    // EdgeConv2 -> out (E x 1), sl[1]
    ec_kernel<0><<<EB, 128, sh2>>>((const float*)px2, ei, (const float*)pef1,
                                   e2w0, e2b0, e2wh, e2bh, e2wc, e2bc,
                                   out, 1);
    if (out_size > NE) fin_kernel<<<1, 1>>>(out);
}

// round 6
// speedup vs baseline: 1.1158x; 1.1158x over previous
#include <cuda_runtime.h>

#define NN 100000
#define NE 600000
#define CIN 16
#define HW 48
#define NL 5
#define EB ((NE + 127) / 128)

typedef unsigned long long u64;

// ---- scratch (device globals: allocation-guard safe) ----
__device__ float  g_x1[NN * CIN];
__device__ float  g_x2[NN * CIN];
__device__ float  g_agg[NN * CIN];
__device__ float  g_cnt[NN];
__device__ float  g_ef1[(size_t)NE * HW];   // 115 MB intermediate edge features
__device__ double g_sl[2];

// ---- f32x2 helpers ----
__device__ __forceinline__ u64 fma2(u64 a, u64 b, u64 c) {
    u64 d;
    asm("fma.rn.f32x2 %0,%1,%2,%3;" : "=l"(d) : "l"(a), "l"(b), "l"(c));
    return d;
}
__device__ __forceinline__ u64 bcast2(float v) {   // pack (v,v) in one MOV.64
    u64 r;
    asm("mov.b64 %0,{%1,%1};" : "=l"(r) : "f"(v));
    return r;
}
union Q4 { float4 f4; u64 u[2]; };     // LDS.128 quad -> two aligned f32x2 pairs (no MOVs)
union P2 { u64 u; float2 f; };         // unpack pair (register-alias, free)

// ---------------------------------------------------------------------------
__global__ void zero_kernel(int phase) {
    int i = blockIdx.x * blockDim.x + threadIdx.x;
    if (i < NN * CIN) g_agg[i] = 0.f;
    if (i < NN)       g_cnt[i] = 0.f;
    if (phase == 0 && i < 2) g_sl[i] = 0.0;
}

// ---------------------------------------------------------------------------
// NodeConv message + scatter (f32x2-packed MLP: 16 outputs = 8 pair-accs).
__global__ __launch_bounds__(128) void nc_kernel(
    const float* __restrict__ x, const int* __restrict__ ei,
    const float* __restrict__ ang,
    const float* __restrict__ w0, const float* __restrict__ b0,
    const float* __restrict__ wh, const float* __restrict__ bh)
{
    __shared__ __align__(16) float sw0[33 * 16];
    __shared__ __align__(16) float sb0[16];
    __shared__ __align__(16) float swh[5 * 16 * 16];
    __shared__ __align__(16) float sbh[5 * 16];
    int t = threadIdx.x;
    for (int i = t; i < 33 * 16; i += 128) sw0[i] = w0[i];
    for (int i = t; i < 16;      i += 128) sb0[i] = b0[i];
    for (int i = t; i < 5 * 256; i += 128) swh[i] = wh[i];
    for (int i = t; i < 80;      i += 128) sbh[i] = bh[i];
    __syncthreads();

    int e = blockIdx.x * 128 + t;
    if (e >= NE) return;
    int s = ei[e];
    int d = ei[NE + e];

    float in[33];
    const float4* xd4 = (const float4*)(x + (size_t)d * CIN);
    const float4* xs4 = (const float4*)(x + (size_t)s * CIN);
    #pragma unroll
    for (int q = 0; q < 4; q++) {
        float4 v = xd4[q];
        in[q * 4 + 0] = v.x; in[q * 4 + 1] = v.y; in[q * 4 + 2] = v.z; in[q * 4 + 3] = v.w;
    }
    #pragma unroll
    for (int q = 0; q < 4; q++) {
        float4 v = xs4[q];
        in[16 + q * 4 + 0] = v.x; in[16 + q * 4 + 1] = v.y;
        in[16 + q * 4 + 2] = v.z; in[16 + q * 4 + 3] = v.w;
    }
    in[32] = ang[e];

    u64 acc[8];
    float h[16];
    #pragma unroll
    for (int jp = 0; jp < 8; jp++) acc[jp] = *(const u64*)(sb0 + 2 * jp);
    #pragma unroll
    for (int k = 0; k < 33; k++) {
        u64 vp = bcast2(in[k]);
        const float4* wr = (const float4*)(sw0 + k * 16);
        #pragma unroll
        for (int q = 0; q < 4; q++) {
            Q4 w; w.f4 = wr[q];
            acc[2 * q + 0] = fma2(vp, w.u[0], acc[2 * q + 0]);
            acc[2 * q + 1] = fma2(vp, w.u[1], acc[2 * q + 1]);
        }
    }
    #pragma unroll
    for (int jp = 0; jp < 8; jp++) {
        P2 p; p.u = acc[jp];
        h[2 * jp + 0] = fmaxf(p.f.x, 0.f);
        h[2 * jp + 1] = fmaxf(p.f.y, 0.f);
    }

    #pragma unroll 1
    for (int l = 0; l < NL; l++) {
        const float* wl = swh + l * 256;
        const float* bl = sbh + l * 16;
        #pragma unroll
        for (int jp = 0; jp < 8; jp++) acc[jp] = *(const u64*)(bl + 2 * jp);
        #pragma unroll
        for (int k = 0; k < 16; k++) {
            u64 vp = bcast2(h[k]);
            const float4* wr = (const float4*)(wl + k * 16);
            #pragma unroll
            for (int q = 0; q < 4; q++) {
                Q4 w; w.f4 = wr[q];
                acc[2 * q + 0] = fma2(vp, w.u[0], acc[2 * q + 0]);
                acc[2 * q + 1] = fma2(vp, w.u[1], acc[2 * q + 1]);
            }
        }
        #pragma unroll
        for (int jp = 0; jp < 8; jp++) {
            P2 p; p.u = acc[jp];
            h[2 * jp + 0] = fmaxf(p.f.x, 0.f);
            h[2 * jp + 1] = fmaxf(p.f.y, 0.f);
        }
    }

    #pragma unroll
    for (int j = 0; j < 16; j++) atomicAdd(&g_agg[(size_t)d * CIN + j], h[j]);
    atomicAdd(&g_cnt[d], 1.f);
}

// ---------------------------------------------------------------------------
__global__ void div_kernel(float* __restrict__ out) {
    int i = blockIdx.x * blockDim.x + threadIdx.x;
    if (i >= NN * CIN) return;
    float c = g_cnt[i / CIN];
    out[i] = g_agg[i] / fmaxf(c, 1.f);
}

// ---------------------------------------------------------------------------
// EdgeConv, f32x2-packed. Inputs (32f) + pass-0 result f1 (48f) are stashed in
// per-thread smem slots [k*128+t] (conflict-free) to keep registers <= ~160.
// IS_EC1=1: combine [fe, action](49) -> 48, out = g_ef1
// IS_EC1=0: combine [fe, ef1](96)   -> 1,  out = d_out
template <int IS_EC1>
__global__ __launch_bounds__(128) void ec_kernel(
    const float* __restrict__ x, const int* __restrict__ ei,
    const float* __restrict__ extra,
    const float* __restrict__ w0, const float* __restrict__ b0,
    const float* __restrict__ wh, const float* __restrict__ bh,
    const float* __restrict__ wc, const float* __restrict__ bc,
    float* __restrict__ out, int sli)
{
    extern __shared__ float smem[];
    const int WC = IS_EC1 ? 49 * 48 : 96;
    const int BC = IS_EC1 ? 48 : 1;
    const int BCPAD = IS_EC1 ? 48 : 16;
    float* sw0   = smem;                   // 1536   (16B aligned)
    float* sb0   = sw0 + 1536;             // 48
    float* swh   = sb0 + 48;               // 11520  (byte off 6336, 16B aligned)
    float* sbh   = swh + 11520;            // 240
    float* swc   = sbh + 240;              // WC     (byte off 53376, 16B aligned)
    float* sbc   = swc + WC;               // BCPAD
    float* stash = sbc + BCPAD;            // 32*128 per-thread input slots
    float* sf1   = stash + 32 * 128;       // 48*128 per-thread f1 slots

    int t = threadIdx.x;
    for (int i = t; i < 1536;  i += 128) sw0[i] = w0[i];
    for (int i = t; i < 48;    i += 128) sb0[i] = b0[i];
    for (int i = t; i < 11520; i += 128) swh[i] = wh[i];
    for (int i = t; i < 240;   i += 128) sbh[i] = bh[i];
    for (int i = t; i < WC;    i += 128) swc[i] = wc[i];
    for (int i = t; i < BC;    i += 128) sbc[i] = bc[i];

    int e = blockIdx.x * 128 + t;
    bool active = (e < NE);
    if (active) {
        int s = ei[e];
        int d = ei[NE + e];
        // stash = [xd(16), xs(16)]  (pass0 concat order; pass1 = index XOR 16)
        const float4* a4 = (const float4*)(x + (size_t)d * CIN);
        const float4* b4 = (const float4*)(x + (size_t)s * CIN);
        #pragma unroll
        for (int q = 0; q < 4; q++) {
            float4 v = a4[q];
            stash[(q * 4 + 0) * 128 + t] = v.x; stash[(q * 4 + 1) * 128 + t] = v.y;
            stash[(q * 4 + 2) * 128 + t] = v.z; stash[(q * 4 + 3) * 128 + t] = v.w;
        }
        #pragma unroll
        for (int q = 0; q < 4; q++) {
            float4 v = b4[q];
            stash[(16 + q * 4 + 0) * 128 + t] = v.x; stash[(16 + q * 4 + 1) * 128 + t] = v.y;
            stash[(16 + q * 4 + 2) * 128 + t] = v.z; stash[(16 + q * 4 + 3) * 128 + t] = v.w;
        }
    }
    __syncthreads();

    float sq = 0.f;
    if (active) {
        float h[48];
        u64 acc[24];

        #pragma unroll 1
        for (int pass = 0; pass < 2; pass++) {
            int px = pass ? 16 : 0;
            // ---- layer 0: 32 -> 48 ----
            #pragma unroll
            for (int jp = 0; jp < 24; jp++) acc[jp] = *(const u64*)(sb0 + 2 * jp);
            #pragma unroll
            for (int k = 0; k < 32; k++) {
                float v = stash[(k ^ px) * 128 + t];
                u64 vp = bcast2(v);
                const float4* wr = (const float4*)(sw0 + k * 48);
                #pragma unroll
                for (int q = 0; q < 12; q++) {
                    Q4 w; w.f4 = wr[q];
                    acc[2 * q + 0] = fma2(vp, w.u[0], acc[2 * q + 0]);
                    acc[2 * q + 1] = fma2(vp, w.u[1], acc[2 * q + 1]);
                }
            }
            #pragma unroll
            for (int jp = 0; jp < 24; jp++) {
                P2 p; p.u = acc[jp];
                h[2 * jp + 0] = fmaxf(p.f.x, 0.f);
                h[2 * jp + 1] = fmaxf(p.f.y, 0.f);
            }
            // ---- hidden layers: 48 -> 48, x5 ----
            #pragma unroll 1
            for (int l = 0; l < NL; l++) {
                const float* wl = swh + l * 2304;
                const float* bl = sbh + l * 48;
                #pragma unroll
                for (int jp = 0; jp < 24; jp++) acc[jp] = *(const u64*)(bl + 2 * jp);
                #pragma unroll
                for (int k = 0; k < 48; k++) {
                    u64 vp = bcast2(h[k]);
                    const float4* wr = (const float4*)(wl + k * 48);
                    #pragma unroll
                    for (int q = 0; q < 12; q++) {
                        Q4 w; w.f4 = wr[q];
                        acc[2 * q + 0] = fma2(vp, w.u[0], acc[2 * q + 0]);
                        acc[2 * q + 1] = fma2(vp, w.u[1], acc[2 * q + 1]);
                    }
                }
                #pragma unroll
                for (int jp = 0; jp < 24; jp++) {
                    P2 p; p.u = acc[jp];
                    h[2 * jp + 0] = fmaxf(p.f.x, 0.f);
                    h[2 * jp + 1] = fmaxf(p.f.y, 0.f);
                }
            }
            if (pass == 0) {
                #pragma unroll
                for (int j = 0; j < 48; j++) sf1[j * 128 + t] = h[j];
            }
        }

        // ---- side loss + fe (fe overwrites h) ----
        #pragma unroll
        for (int j = 0; j < 48; j++) {
            float a = sf1[j * 128 + t];
            float dl = a - h[j];
            sq += dl * dl;
            h[j] = 0.5f * (a + h[j]);
        }

        if (IS_EC1) {
            float aact = extra[e];
            u64 o[24];
            #pragma unroll
            for (int jp = 0; jp < 24; jp++) o[jp] = *(const u64*)(sbc + 2 * jp);
            {   // action row (row 48)
                u64 ap = bcast2(aact);
                const float4* wr = (const float4*)(swc + 48 * 48);
                #pragma unroll
                for (int q = 0; q < 12; q++) {
                    Q4 w; w.f4 = wr[q];
                    o[2 * q + 0] = fma2(ap, w.u[0], o[2 * q + 0]);
                    o[2 * q + 1] = fma2(ap, w.u[1], o[2 * q + 1]);
                }
            }
            #pragma unroll
            for (int k = 0; k < 48; k++) {
                u64 vp = bcast2(h[k]);
                const float4* wr = (const float4*)(swc + k * 48);
                #pragma unroll
                for (int q = 0; q < 12; q++) {
                    Q4 w; w.f4 = wr[q];
                    o[2 * q + 0] = fma2(vp, w.u[0], o[2 * q + 0]);
                    o[2 * q + 1] = fma2(vp, w.u[1], o[2 * q + 1]);
                }
            }
            #pragma unroll
            for (int q = 0; q < 12; q++) {
                P2 p0; p0.u = o[2 * q + 0];
                P2 p1; p1.u = o[2 * q + 1];
                *(float4*)(out + (size_t)e * 48 + q * 4) =
                    make_float4(p0.f.x, p0.f.y, p1.f.x, p1.f.y);
            }
        } else {
            float o = sbc[0];
            #pragma unroll
            for (int k = 0; k < 48; k++) o += h[k] * swc[k];
            const float4* ef = (const float4*)(extra + (size_t)e * 48);
            #pragma unroll
            for (int q = 0; q < 12; q++) {
                float4 v = ef[q];
                o += v.x * swc[48 + q * 4 + 0];
                o += v.y * swc[48 + q * 4 + 1];
                o += v.z * swc[48 + q * 4 + 2];
                o += v.w * swc[48 + q * 4 + 3];
            }
            out[e] = o;
        }
    }

    // side-loss reduction: warp shfl -> double atomic
    #pragma unroll
    for (int off = 16; off; off >>= 1)
        sq += __shfl_xor_sync(0xffffffffu, sq, off);
    if ((t & 31) == 0)
        atomicAdd(&g_sl[sli], (double)sq);
}

// ---------------------------------------------------------------------------
__global__ void fin_kernel(float* __restrict__ out) {
    double inv = 1.0 / ((double)NE * 48.0);
    out[NE] = (float)(0.5 * (g_sl[0] * inv + g_sl[1] * inv));
}

// ---------------------------------------------------------------------------
extern "C" void kernel_launch(void* const* d_in, const int* in_sizes, int n_in,
                              void* d_out, int out_size)
{
    const float* nf   = (const float*)d_in[0];
    const int*   ei   = (const int*)d_in[1];
    const float* ang  = (const float*)d_in[2];
    const float* act  = (const float*)d_in[4];
    const float* n1w0 = (const float*)d_in[5],  *n1b0 = (const float*)d_in[6];
    const float* n1wh = (const float*)d_in[7],  *n1bh = (const float*)d_in[8];
    const float* n2w0 = (const float*)d_in[9],  *n2b0 = (const float*)d_in[10];
    const float* n2wh = (const float*)d_in[11], *n2bh = (const float*)d_in[12];
    const float* e1w0 = (const float*)d_in[13], *e1b0 = (const float*)d_in[14];
    const float* e1wh = (const float*)d_in[15], *e1bh = (const float*)d_in[16];
    const float* e1wc = (const float*)d_in[17], *e1bc = (const float*)d_in[18];
    const float* e2w0 = (const float*)d_in[19], *e2b0 = (const float*)d_in[20];
    const float* e2wh = (const float*)d_in[21], *e2bh = (const float*)d_in[22];
    const float* e2wc = (const float*)d_in[23], *e2bc = (const float*)d_in[24];
    float* out = (float*)d_out;

    void *px1, *px2, *pef1;
    cudaGetSymbolAddress(&px1, g_x1);
    cudaGetSymbolAddress(&px2, g_x2);
    cudaGetSymbolAddress(&pef1, g_ef1);

    // smem: weights + BCPAD + stash(32*128) + sf1(48*128)
    size_t sh1 = (size_t)(1536 + 48 + 11520 + 240 + 49 * 48 + 48 + 32 * 128 + 48 * 128) * sizeof(float);
    size_t sh2 = (size_t)(1536 + 48 + 11520 + 240 + 96 + 16 + 32 * 128 + 48 * 128) * sizeof(float);
    cudaFuncSetAttribute(ec_kernel<1>, cudaFuncAttributeMaxDynamicSharedMemorySize, (int)sh1);
    cudaFuncSetAttribute(ec_kernel<0>, cudaFuncAttributeMaxDynamicSharedMemorySize, (int)sh2);

    // NodeConv1 -> x1
    zero_kernel<<<6250, 256>>>(0);
    nc_kernel<<<EB, 128>>>(nf, ei, ang, n1w0, n1b0, n1wh, n1bh);
    div_kernel<<<6250, 256>>>((float*)px1);
    // EdgeConv1 -> ef1 (E x 48), sl[0]
    ec_kernel<1><<<EB, 128, sh1>>>((const float*)px1, ei, act,
                                   e1w0, e1b0, e1wh, e1bh, e1wc, e1bc,
                                   (float*)pef1, 0);
    // NodeConv2 -> x2
    zero_kernel<<<6250, 256>>>(1);
    nc_kernel<<<EB, 128>>>((const float*)px1, ei, ang, n2w0, n2b0, n2wh, n2bh);
    div_kernel<<<6250, 256>>>((float*)px2);
    // EdgeConv2 -> out (E x 1), sl[1]
    ec_kernel<0><<<EB, 128, sh2>>>((const float*)px2, ei, (const float*)pef1,
                                   e2w0, e2b0, e2wh, e2bh, e2wc, e2bc,
                                   out, 1);
    if (out_size > NE) fin_kernel<<<1, 1>>>(out);
}

// round 7
// speedup vs baseline: 1.5736x; 1.4103x over previous
#include <cuda_runtime.h>

#define NN 100000
#define NE 600000
#define CIN 16
#define HW 48
#define NL 5
#define EB ((NE + 127) / 128)

typedef unsigned long long u64;

// ---- scratch (device globals: allocation-guard safe) ----
__device__ float  g_x1[NN * CIN];
__device__ float  g_x2[NN * CIN];
__device__ float  g_agg[NN * CIN];
__device__ float  g_cnt[NN];
__device__ float  g_ef1[(size_t)NE * HW];   // 115 MB intermediate edge features
__device__ double g_sl[2];

// ---- f32x2 helpers ----
__device__ __forceinline__ u64 fma2(u64 a, u64 b, u64 c) {
    u64 d;
    asm("fma.rn.f32x2 %0,%1,%2,%3;" : "=l"(d) : "l"(a), "l"(b), "l"(c));
    return d;
}
__device__ __forceinline__ u64 bcast2(float v) {   // pack (v,v) in one MOV.64
    u64 r;
    asm("mov.b64 %0,{%1,%1};" : "=l"(r) : "f"(v));
    return r;
}
union Q4 { float4 f4; u64 u[2]; };     // LDS.128 quad -> two aligned f32x2 pairs
union P2 { u64 u; float2 f; };         // unpack pair (register-alias, free)

// ---------------------------------------------------------------------------
__global__ void zero_kernel(int phase) {
    int i = blockIdx.x * blockDim.x + threadIdx.x;
    if (i < NN * CIN) g_agg[i] = 0.f;
    if (i < NN)       g_cnt[i] = 0.f;
    if (phase == 0 && i < 2) g_sl[i] = 0.0;
}

// ---------------------------------------------------------------------------
// NodeConv message + scatter (f32x2-packed MLP: 16 outputs = 8 pair-accs).
__global__ __launch_bounds__(128) void nc_kernel(
    const float* __restrict__ x, const int* __restrict__ ei,
    const float* __restrict__ ang,
    const float* __restrict__ w0, const float* __restrict__ b0,
    const float* __restrict__ wh, const float* __restrict__ bh)
{
    __shared__ __align__(16) float sw0[33 * 16];
    __shared__ __align__(16) float sb0[16];
    __shared__ __align__(16) float swh[5 * 16 * 16];
    __shared__ __align__(16) float sbh[5 * 16];
    int t = threadIdx.x;
    for (int i = t; i < 33 * 16; i += 128) sw0[i] = w0[i];
    for (int i = t; i < 16;      i += 128) sb0[i] = b0[i];
    for (int i = t; i < 5 * 256; i += 128) swh[i] = wh[i];
    for (int i = t; i < 80;      i += 128) sbh[i] = bh[i];
    __syncthreads();

    int e = blockIdx.x * 128 + t;
    if (e >= NE) return;
    int s = ei[e];
    int d = ei[NE + e];

    float in[33];
    const float4* xd4 = (const float4*)(x + (size_t)d * CIN);
    const float4* xs4 = (const float4*)(x + (size_t)s * CIN);
    #pragma unroll
    for (int q = 0; q < 4; q++) {
        float4 v = xd4[q];
        in[q * 4 + 0] = v.x; in[q * 4 + 1] = v.y; in[q * 4 + 2] = v.z; in[q * 4 + 3] = v.w;
    }
    #pragma unroll
    for (int q = 0; q < 4; q++) {
        float4 v = xs4[q];
        in[16 + q * 4 + 0] = v.x; in[16 + q * 4 + 1] = v.y;
        in[16 + q * 4 + 2] = v.z; in[16 + q * 4 + 3] = v.w;
    }
    in[32] = ang[e];

    u64 acc[8];
    float h[16];
    #pragma unroll
    for (int jp = 0; jp < 8; jp++) acc[jp] = *(const u64*)(sb0 + 2 * jp);
    #pragma unroll
    for (int k = 0; k < 33; k++) {
        u64 vp = bcast2(in[k]);
        const float4* wr = (const float4*)(sw0 + k * 16);
        #pragma unroll
        for (int q = 0; q < 4; q++) {
            Q4 w; w.f4 = wr[q];
            acc[2 * q + 0] = fma2(vp, w.u[0], acc[2 * q + 0]);
            acc[2 * q + 1] = fma2(vp, w.u[1], acc[2 * q + 1]);
        }
    }
    #pragma unroll
    for (int jp = 0; jp < 8; jp++) {
        P2 p; p.u = acc[jp];
        h[2 * jp + 0] = fmaxf(p.f.x, 0.f);
        h[2 * jp + 1] = fmaxf(p.f.y, 0.f);
    }

    #pragma unroll 1
    for (int l = 0; l < NL; l++) {
        const float* wl = swh + l * 256;
        const float* bl = sbh + l * 16;
        #pragma unroll
        for (int jp = 0; jp < 8; jp++) acc[jp] = *(const u64*)(bl + 2 * jp);
        #pragma unroll
        for (int k = 0; k < 16; k++) {
            u64 vp = bcast2(h[k]);
            const float4* wr = (const float4*)(wl + k * 16);
            #pragma unroll
            for (int q = 0; q < 4; q++) {
                Q4 w; w.f4 = wr[q];
                acc[2 * q + 0] = fma2(vp, w.u[0], acc[2 * q + 0]);
                acc[2 * q + 1] = fma2(vp, w.u[1], acc[2 * q + 1]);
            }
        }
        #pragma unroll
        for (int jp = 0; jp < 8; jp++) {
            P2 p; p.u = acc[jp];
            h[2 * jp + 0] = fmaxf(p.f.x, 0.f);
            h[2 * jp + 1] = fmaxf(p.f.y, 0.f);
        }
    }

    #pragma unroll
    for (int j = 0; j < 16; j++) atomicAdd(&g_agg[(size_t)d * CIN + j], h[j]);
    atomicAdd(&g_cnt[d], 1.f);
}

// ---------------------------------------------------------------------------
__global__ void div_kernel(float* __restrict__ out) {
    int i = blockIdx.x * blockDim.x + threadIdx.x;
    if (i >= NN * CIN) return;
    float c = g_cnt[i / CIN];
    out[i] = g_agg[i] / fmaxf(c, 1.f);
}

// ---------------------------------------------------------------------------
// EdgeConv, f32x2-packed, BOTH MLP passes fused in one k-loop:
// each weight quad is loaded ONCE from smem and feeds 4 FFMA2 (acc0 for f1,
// acc1 for f2). Halves LDS traffic vs per-pass evaluation and removes the
// f1 stash (f1 = h0 stays in registers).
// IS_EC1=1: combine [fe, action](49) -> 48, out = g_ef1
// IS_EC1=0: combine [fe, ef1](96)   -> 1,  out = d_out
template <int IS_EC1>
__global__ __launch_bounds__(128, 2) void ec_kernel(
    const float* __restrict__ x, const int* __restrict__ ei,
    const float* __restrict__ extra,
    const float* __restrict__ w0, const float* __restrict__ b0,
    const float* __restrict__ wh, const float* __restrict__ bh,
    const float* __restrict__ wc, const float* __restrict__ bc,
    float* __restrict__ out, int sli)
{
    extern __shared__ float smem[];
    const int WC = IS_EC1 ? 49 * 48 : 96;
    const int BC = IS_EC1 ? 48 : 1;
    const int BCPAD = IS_EC1 ? 48 : 16;
    float* sw0   = smem;                   // 1536   (16B aligned)
    float* sb0   = sw0 + 1536;             // 48
    float* swh   = sb0 + 48;               // 11520  (byte off 6336, 16B aligned)
    float* sbh   = swh + 11520;            // 240
    float* swc   = sbh + 240;              // WC     (byte off 53376, 16B aligned)
    float* sbc   = swc + WC;               // BCPAD
    float* stash = sbc + BCPAD;            // 32*128 per-thread input slots

    int t = threadIdx.x;
    for (int i = t; i < 1536;  i += 128) sw0[i] = w0[i];
    for (int i = t; i < 48;    i += 128) sb0[i] = b0[i];
    for (int i = t; i < 11520; i += 128) swh[i] = wh[i];
    for (int i = t; i < 240;   i += 128) sbh[i] = bh[i];
    for (int i = t; i < WC;    i += 128) swc[i] = wc[i];
    for (int i = t; i < BC;    i += 128) sbc[i] = bc[i];

    int e = blockIdx.x * 128 + t;
    bool active = (e < NE);
    if (active) {
        int s = ei[e];
        int d = ei[NE + e];
        // stash = [xd(16), xs(16)]  (pass0 concat order; pass1 = index XOR 16)
        const float4* a4 = (const float4*)(x + (size_t)d * CIN);
        const float4* b4 = (const float4*)(x + (size_t)s * CIN);
        #pragma unroll
        for (int q = 0; q < 4; q++) {
            float4 v = a4[q];
            stash[(q * 4 + 0) * 128 + t] = v.x; stash[(q * 4 + 1) * 128 + t] = v.y;
            stash[(q * 4 + 2) * 128 + t] = v.z; stash[(q * 4 + 3) * 128 + t] = v.w;
        }
        #pragma unroll
        for (int q = 0; q < 4; q++) {
            float4 v = b4[q];
            stash[(16 + q * 4 + 0) * 128 + t] = v.x; stash[(16 + q * 4 + 1) * 128 + t] = v.y;
            stash[(16 + q * 4 + 2) * 128 + t] = v.z; stash[(16 + q * 4 + 3) * 128 + t] = v.w;
        }
    }
    __syncthreads();

    float sq = 0.f;
    if (active) {
        float h0[48], h1[48];
        u64 acc0[24], acc1[24];

        // ---- layer 0: 32 -> 48, both passes share every weight quad ----
        #pragma unroll
        for (int jp = 0; jp < 24; jp++) {
            u64 b = *(const u64*)(sb0 + 2 * jp);
            acc0[jp] = b; acc1[jp] = b;
        }
        #pragma unroll
        for (int k = 0; k < 32; k++) {
            u64 p0 = bcast2(stash[k * 128 + t]);
            u64 p1 = bcast2(stash[(k ^ 16) * 128 + t]);
            const float4* wr = (const float4*)(sw0 + k * 48);
            #pragma unroll
            for (int q = 0; q < 12; q++) {
                Q4 w; w.f4 = wr[q];
                acc0[2 * q + 0] = fma2(p0, w.u[0], acc0[2 * q + 0]);
                acc0[2 * q + 1] = fma2(p0, w.u[1], acc0[2 * q + 1]);
                acc1[2 * q + 0] = fma2(p1, w.u[0], acc1[2 * q + 0]);
                acc1[2 * q + 1] = fma2(p1, w.u[1], acc1[2 * q + 1]);
            }
        }
        #pragma unroll
        for (int jp = 0; jp < 24; jp++) {
            P2 p; p.u = acc0[jp];
            h0[2 * jp + 0] = fmaxf(p.f.x, 0.f);
            h0[2 * jp + 1] = fmaxf(p.f.y, 0.f);
            P2 r; r.u = acc1[jp];
            h1[2 * jp + 0] = fmaxf(r.f.x, 0.f);
            h1[2 * jp + 1] = fmaxf(r.f.y, 0.f);
        }

        // ---- hidden layers: 48 -> 48, x5, fused passes ----
        #pragma unroll 1
        for (int l = 0; l < NL; l++) {
            const float* wl = swh + l * 2304;
            const float* bl = sbh + l * 48;
            #pragma unroll
            for (int jp = 0; jp < 24; jp++) {
                u64 b = *(const u64*)(bl + 2 * jp);
                acc0[jp] = b; acc1[jp] = b;
            }
            #pragma unroll
            for (int k = 0; k < 48; k++) {
                u64 p0 = bcast2(h0[k]);
                u64 p1 = bcast2(h1[k]);
                const float4* wr = (const float4*)(wl + k * 48);
                #pragma unroll
                for (int q = 0; q < 12; q++) {
                    Q4 w; w.f4 = wr[q];
                    acc0[2 * q + 0] = fma2(p0, w.u[0], acc0[2 * q + 0]);
                    acc0[2 * q + 1] = fma2(p0, w.u[1], acc0[2 * q + 1]);
                    acc1[2 * q + 0] = fma2(p1, w.u[0], acc1[2 * q + 0]);
                    acc1[2 * q + 1] = fma2(p1, w.u[1], acc1[2 * q + 1]);
                }
            }
            #pragma unroll
            for (int jp = 0; jp < 24; jp++) {
                P2 p; p.u = acc0[jp];
                h0[2 * jp + 0] = fmaxf(p.f.x, 0.f);
                h0[2 * jp + 1] = fmaxf(p.f.y, 0.f);
                P2 r; r.u = acc1[jp];
                h1[2 * jp + 0] = fmaxf(r.f.x, 0.f);
                h1[2 * jp + 1] = fmaxf(r.f.y, 0.f);
            }
        }

        // ---- side loss + fe (fe overwrites h0) ----
        #pragma unroll
        for (int j = 0; j < 48; j++) {
            float dl = h0[j] - h1[j];
            sq += dl * dl;
            h0[j] = 0.5f * (h0[j] + h1[j]);
        }

        if (IS_EC1) {
            float aact = extra[e];
            u64 o[24];
            #pragma unroll
            for (int jp = 0; jp < 24; jp++) o[jp] = *(const u64*)(sbc + 2 * jp);
            {   // action row (row 48)
                u64 ap = bcast2(aact);
                const float4* wr = (const float4*)(swc + 48 * 48);
                #pragma unroll
                for (int q = 0; q < 12; q++) {
                    Q4 w; w.f4 = wr[q];
                    o[2 * q + 0] = fma2(ap, w.u[0], o[2 * q + 0]);
                    o[2 * q + 1] = fma2(ap, w.u[1], o[2 * q + 1]);
                }
            }
            #pragma unroll
            for (int k = 0; k < 48; k++) {
                u64 vp = bcast2(h0[k]);
                const float4* wr = (const float4*)(swc + k * 48);
                #pragma unroll
                for (int q = 0; q < 12; q++) {
                    Q4 w; w.f4 = wr[q];
                    o[2 * q + 0] = fma2(vp, w.u[0], o[2 * q + 0]);
                    o[2 * q + 1] = fma2(vp, w.u[1], o[2 * q + 1]);
                }
            }
            #pragma unroll
            for (int q = 0; q < 12; q++) {
                P2 p0; p0.u = o[2 * q + 0];
                P2 p1; p1.u = o[2 * q + 1];
                *(float4*)(out + (size_t)e * 48 + q * 4) =
                    make_float4(p0.f.x, p0.f.y, p1.f.x, p1.f.y);
            }
        } else {
            float o = sbc[0];
            #pragma unroll
            for (int k = 0; k < 48; k++) o += h0[k] * swc[k];
            const float4* ef = (const float4*)(extra + (size_t)e * 48);
            #pragma unroll
            for (int q = 0; q < 12; q++) {
                float4 v = ef[q];
                o += v.x * swc[48 + q * 4 + 0];
                o += v.y * swc[48 + q * 4 + 1];
                o += v.z * swc[48 + q * 4 + 2];
                o += v.w * swc[48 + q * 4 + 3];
            }
            out[e] = o;
        }
    }

    // side-loss reduction: warp shfl -> double atomic
    #pragma unroll
    for (int off = 16; off; off >>= 1)
        sq += __shfl_xor_sync(0xffffffffu, sq, off);
    if ((t & 31) == 0)
        atomicAdd(&g_sl[sli], (double)sq);
}

// ---------------------------------------------------------------------------
__global__ void fin_kernel(float* __restrict__ out) {
    double inv = 1.0 / ((double)NE * 48.0);
    out[NE] = (float)(0.5 * (g_sl[0] * inv + g_sl[1] * inv));
}

// ---------------------------------------------------------------------------
extern "C" void kernel_launch(void* const* d_in, const int* in_sizes, int n_in,
                              void* d_out, int out_size)
{
    const float* nf   = (const float*)d_in[0];
    const int*   ei   = (const int*)d_in[1];
    const float* ang  = (const float*)d_in[2];
    const float* act  = (const float*)d_in[4];
    const float* n1w0 = (const float*)d_in[5],  *n1b0 = (const float*)d_in[6];
    const float* n1wh = (const float*)d_in[7],  *n1bh = (const float*)d_in[8];
    const float* n2w0 = (const float*)d_in[9],  *n2b0 = (const float*)d_in[10];
    const float* n2wh = (const float*)d_in[11], *n2bh = (const float*)d_in[12];
    const float* e1w0 = (const float*)d_in[13], *e1b0 = (const float*)d_in[14];
    const float* e1wh = (const float*)d_in[15], *e1bh = (const float*)d_in[16];
    const float* e1wc = (const float*)d_in[17], *e1bc = (const float*)d_in[18];
    const float* e2w0 = (const float*)d_in[19], *e2b0 = (const float*)d_in[20];
    const float* e2wh = (const float*)d_in[21], *e2bh = (const float*)d_in[22];
    const float* e2wc = (const float*)d_in[23], *e2bc = (const float*)d_in[24];
    float* out = (float*)d_out;

    void *px1, *px2, *pef1;
    cudaGetSymbolAddress(&px1, g_x1);
    cudaGetSymbolAddress(&px2, g_x2);
    cudaGetSymbolAddress(&pef1, g_ef1);

    // smem: weights + BCPAD + stash(32*128)
    size_t sh1 = (size_t)(1536 + 48 + 11520 + 240 + 49 * 48 + 48 + 32 * 128) * sizeof(float);
    size_t sh2 = (size_t)(1536 + 48 + 11520 + 240 + 96 + 16 + 32 * 128) * sizeof(float);
    cudaFuncSetAttribute(ec_kernel<1>, cudaFuncAttributeMaxDynamicSharedMemorySize, (int)sh1);
    cudaFuncSetAttribute(ec_kernel<0>, cudaFuncAttributeMaxDynamicSharedMemorySize, (int)sh2);
    // ensure the carveout can host 2 blocks/SM (2 x ~79KB)
    cudaFuncSetAttribute(ec_kernel<1>, cudaFuncAttributePreferredSharedMemoryCarveout, 100);
    cudaFuncSetAttribute(ec_kernel<0>, cudaFuncAttributePreferredSharedMemoryCarveout, 100);

    // NodeConv1 -> x1
    zero_kernel<<<6250, 256>>>(0);
    nc_kernel<<<EB, 128>>>(nf, ei, ang, n1w0, n1b0, n1wh, n1bh);
    div_kernel<<<6250, 256>>>((float*)px1);
    // EdgeConv1 -> ef1 (E x 48), sl[0]
    ec_kernel<1><<<EB, 128, sh1>>>((const float*)px1, ei, act,
                                   e1w0, e1b0, e1wh, e1bh, e1wc, e1bc,
                                   (float*)pef1, 0);
    // NodeConv2 -> x2
    zero_kernel<<<6250, 256>>>(1);
    nc_kernel<<<EB, 128>>>((const float*)px1, ei, ang, n2w0, n2b0, n2wh, n2bh);
    div_kernel<<<6250, 256>>>((float*)px2);
    // EdgeConv2 -> out (E x 1), sl[1]
    ec_kernel<0><<<EB, 128, sh2>>>((const float*)px2, ei, (const float*)pef1,
                                   e2w0, e2b0, e2wh, e2bh, e2wc, e2bc,
                                   out, 1);
    if (out_size > NE) fin_kernel<<<1, 1>>>(out);
}